// round 9
// baseline (speedup 1.0000x reference)
#include <cuda_runtime.h>

typedef unsigned long long u64;

// Packed fp32x2 ops (Blackwell sm_103a). ptxas never auto-fuses these from C++;
// they must come from PTX (SASS_QUICKREF "patterns absent from ptxas output").
__device__ __forceinline__ u64 add2(u64 a, u64 b) {
    u64 d; asm("add.rn.f32x2 %0, %1, %2;" : "=l"(d) : "l"(a), "l"(b)); return d;
}
__device__ __forceinline__ u64 fma2(u64 a, u64 b, u64 c) {
    u64 d; asm("fma.rn.f32x2 %0, %1, %2, %3;" : "=l"(d) : "l"(a), "l"(b), "l"(c)); return d;
}
__device__ __forceinline__ u64 dup_lo(u64 a) {
    u64 d;
    asm("{\n\t.reg .b32 lo, hi;\n\tmov.b64 {lo, hi}, %1;\n\tmov.b64 %0, {lo, lo};\n\t}"
        : "=l"(d) : "l"(a));
    return d;
}
__device__ __forceinline__ u64 dup_hi(u64 a) {
    u64 d;
    asm("{\n\t.reg .b32 lo, hi;\n\tmov.b64 {lo, hi}, %1;\n\tmov.b64 %0, {hi, hi};\n\t}"
        : "=l"(d) : "l"(a));
    return d;
}

#define DIN   112   // input spatial extent (D = H = W)
#define DOUT  111   // output extent per dim (VALID 2-window)
#define MCH   16    // channels
#define TH    4     // output h-rows per block
#define CS4   5     // float4 slots per smem column (4 data + 1 pad -> 80B stride)

// Block: 128 threads. grid = (ceil(111/TH)=28, 111).
// Phase 1: build p[h'][w'][c] = x[d0] + x[d0+1] for (TH+1) h-rows into padded
//          SMEM (80B column stride -> conflict-free LDS.128 in phase 2).
// Phase 2: tid -> (ht = tid>>5 in [0,4), wl = tid&31); each thread computes full
//          16-ch output vectors at w = wl, wl+32, ...: agg = sum of 4 smem
//          columns, then out = agg @ (M/8)^T via f32x2 FMAs (M^T staged in SMEM,
//          broadcast reads, 1/8 window divisor pre-folded).
__global__ __launch_bounds__(128, 4)
void sdd3_kernel(const float* __restrict__ x,
                 const float* __restrict__ M,
                 float* __restrict__ out)
{
    __shared__ float4 sP[(TH + 1) * DIN * CS4];      // 5*112*5*16B = 44800 B
    __shared__ __align__(16) float sM[MCH * MCH];    // transposed, pre-scaled by 1/8

    const int tid = threadIdx.x;
    const int d0 = blockIdx.y;            // output d index: needs input d0, d0+1
    const int h0 = blockIdx.x * TH;       // first output h row of this tile
    const int rows_out = min(TH, DOUT - h0);
    const int rows_in  = rows_out + 1;

    // ---------------- Phase 1: d-pair sums into padded SMEM ----------------
    const size_t slice = (size_t)DIN * DIN * MCH;
    const float4* __restrict__ xa =
        (const float4*)(x + (size_t)d0 * slice + (size_t)h0 * DIN * MCH);
    const float4* __restrict__ xb = (const float4*)((const float*)xa + slice);

    const int n4 = rows_in * DIN * 4;     // float4 elements to stage
    for (int i = tid; i < n4; i += 128) {
        float4 a = xa[i];
        float4 b = xb[i];
        float4 s = make_float4(a.x + b.x, a.y + b.y, a.z + b.z, a.w + b.w);
        sP[(i >> 2) * CS4 + (i & 3)] = s;   // column-padded layout
    }
    // Stage M^T * 0.125: sM[j*16 + i] = M[i*16 + j] / 8
    for (int t = tid; t < MCH * MCH; t += 128) {
        int i = t >> 4, j = t & 15;
        sM[j * MCH + i] = M[t] * 0.125f;
    }
    __syncthreads();

    // ---------------- Phase 2: window combine + f32x2 matmul ----------------
    const int ht = tid >> 5;      // output row within tile
    const int wl = tid & 31;      // starting w lane
    if (ht < rows_out) {
        const char* sbase = (const char*)sP;
        for (int w = wl; w < DOUT; w += 32) {
            const int c00 = (ht * DIN + w) * 80;    // bytes; 80B per column
            const ulonglong2* p00 = (const ulonglong2*)(sbase + c00);
            const ulonglong2* p01 = (const ulonglong2*)(sbase + c00 + 80);
            const ulonglong2* p10 = (const ulonglong2*)(sbase + c00 + DIN * 80);
            const ulonglong2* p11 = (const ulonglong2*)(sbase + c00 + DIN * 80 + 80);

            u64 agg[8];   // agg[p] holds channels (2p, 2p+1) of the window SUM
            #pragma unroll
            for (int k = 0; k < 4; ++k) {
                ulonglong2 a0 = p00[k];
                ulonglong2 a1 = p01[k];
                ulonglong2 b0 = p10[k];
                ulonglong2 b1 = p11[k];
                agg[2 * k]     = add2(add2(a0.x, a1.x), add2(b0.x, b1.x));
                agg[2 * k + 1] = add2(add2(a0.y, a1.y), add2(b0.y, b1.y));
            }

            u64 o[8];     // o[p] = output channels (2p, 2p+1)
            #pragma unroll
            for (int k = 0; k < 8; ++k) o[k] = 0ull;

            #pragma unroll
            for (int jp = 0; jp < 8; ++jp) {
                u64 alo = dup_lo(agg[jp]);   // scalar agg channel j = 2*jp, duplicated
                u64 ahi = dup_hi(agg[jp]);   // scalar agg channel j = 2*jp+1
                const ulonglong2* m0 = (const ulonglong2*)&sM[(2 * jp) * MCH];
                const ulonglong2* m1 = (const ulonglong2*)&sM[(2 * jp + 1) * MCH];
                #pragma unroll
                for (int k = 0; k < 4; ++k) {
                    ulonglong2 mv = m0[k];   // (M/8)^T row j, out channels 4k..4k+3
                    o[2 * k]     = fma2(alo, mv.x, o[2 * k]);
                    o[2 * k + 1] = fma2(alo, mv.y, o[2 * k + 1]);
                }
                #pragma unroll
                for (int k = 0; k < 4; ++k) {
                    ulonglong2 mv = m1[k];
                    o[2 * k]     = fma2(ahi, mv.x, o[2 * k]);
                    o[2 * k + 1] = fma2(ahi, mv.y, o[2 * k + 1]);
                }
            }

            ulonglong2* op = (ulonglong2*)(out +
                (((size_t)d0 * DOUT + (size_t)(h0 + ht)) * DOUT + (size_t)w) * MCH);
            #pragma unroll
            for (int k = 0; k < 4; ++k)
                op[k] = make_ulonglong2(o[2 * k], o[2 * k + 1]);
        }
    }
}

extern "C" void kernel_launch(void* const* d_in, const int* in_sizes, int n_in,
                              void* d_out, int out_size)
{
    const float* x = (const float*)d_in[0];
    const float* M = (const float*)d_in[1];
    // Robustness: detect argument order by size (M is 16*16 = 256 elements).
    if (n_in >= 2 && in_sizes[0] == MCH * MCH) {
        x = (const float*)d_in[1];
        M = (const float*)d_in[0];
    }
    dim3 grid((DOUT + TH - 1) / TH, DOUT);   // (28, 111)
    sdd3_kernel<<<grid, 128>>>(x, M, (float*)d_out);
}